// round 1
// baseline (speedup 1.0000x reference)
#include <cuda_runtime.h>
#include <cstdint>

// Problem constants
#define B_  2
#define L_  16384
#define C_  512
#define H_  16
#define D_  32
#define K_  7
#define SCALE_ 0.17677669529663687f   // 32^-0.5

// Scratch (device globals: no allocation allowed in kernel_launch)
__device__ float g_qkv[(size_t)B_ * L_ * 3 * C_];   // (B*L, 1536)  order (s,h,d)
__device__ float g_ao [(size_t)B_ * L_ * C_];       // (B*L, 512)   order (h,d)

// ---------------------------------------------------------------------------
// GEMM: C[M,N] = A[M,K] @ W[N,K]^T + bias[N]     (both A and W are K-major)
// 128x128 tile, BK=16, 256 threads, 8x8 per-thread micro-tile, fp32.
// Assumes M%128==0, N%128==0, K%16==0 (true here: M=32768, N in {1536,512}, K=512)
// ---------------------------------------------------------------------------
#define BM 128
#define BN 128
#define BK 16

__global__ __launch_bounds__(256) void gemm_nt_bias(
    const float* __restrict__ A, const float* __restrict__ W,
    const float* __restrict__ bias, float* __restrict__ C,
    int M, int N, int K)
{
    __shared__ float As[BK][BM];
    __shared__ float Bs[BK][BN];

    const int tid = threadIdx.x;
    const int bm = blockIdx.y * BM;
    const int bn = blockIdx.x * BN;
    const int tx = tid & 15;        // 0..15  -> N
    const int ty = tid >> 4;        // 0..15  -> M

    const float* Ab = A + (size_t)bm * K;
    const float* Wb = W + (size_t)bn * K;

    float acc[8][8];
#pragma unroll
    for (int i = 0; i < 8; i++)
#pragma unroll
        for (int j = 0; j < 8; j++) acc[i][j] = 0.f;

    for (int k0 = 0; k0 < K; k0 += BK) {
        // Load 128x16 tiles of A and W (float4 each; 2 per thread per matrix)
#pragma unroll
        for (int i = 0; i < 2; i++) {
            int idx = tid + i * 256;          // 0..511
            int row = idx >> 2;               // 0..127
            int c4  = idx & 3;                // 0..3
            float4 va = *(const float4*)(Ab + (size_t)row * K + k0 + c4 * 4);
            As[c4 * 4 + 0][row] = va.x;
            As[c4 * 4 + 1][row] = va.y;
            As[c4 * 4 + 2][row] = va.z;
            As[c4 * 4 + 3][row] = va.w;
            float4 vb = *(const float4*)(Wb + (size_t)row * K + k0 + c4 * 4);
            Bs[c4 * 4 + 0][row] = vb.x;
            Bs[c4 * 4 + 1][row] = vb.y;
            Bs[c4 * 4 + 2][row] = vb.z;
            Bs[c4 * 4 + 3][row] = vb.w;
        }
        __syncthreads();

#pragma unroll
        for (int kk = 0; kk < BK; kk++) {
            float ar[8], br[8];
            *(float4*)(ar + 0) = *(const float4*)&As[kk][ty * 8 + 0];
            *(float4*)(ar + 4) = *(const float4*)&As[kk][ty * 8 + 4];
            *(float4*)(br + 0) = *(const float4*)&Bs[kk][tx * 8 + 0];
            *(float4*)(br + 4) = *(const float4*)&Bs[kk][tx * 8 + 4];
#pragma unroll
            for (int i = 0; i < 8; i++)
#pragma unroll
                for (int j = 0; j < 8; j++)
                    acc[i][j] += ar[i] * br[j];
        }
        __syncthreads();
    }

    // Epilogue: add bias, write as 2 float4 per row
    float bv[8];
#pragma unroll
    for (int j = 0; j < 8; j++) bv[j] = bias[bn + tx * 8 + j];

#pragma unroll
    for (int i = 0; i < 8; i++) {
        size_t row = (size_t)(bm + ty * 8 + i);
        float* cp = C + row * N + bn + tx * 8;
        float4 o0, o1;
        o0.x = acc[i][0] + bv[0]; o0.y = acc[i][1] + bv[1];
        o0.z = acc[i][2] + bv[2]; o0.w = acc[i][3] + bv[3];
        o1.x = acc[i][4] + bv[4]; o1.y = acc[i][5] + bv[5];
        o1.z = acc[i][6] + bv[6]; o1.w = acc[i][7] + bv[7];
        *(float4*)(cp + 0) = o0;
        *(float4*)(cp + 4) = o1;
    }
}

// ---------------------------------------------------------------------------
// Neighborhood attention, K=7, D=32.
// One block = (b, h, tile of 128 positions). K/V rows staged in padded smem.
// One thread per query position; q held in registers.
// ---------------------------------------------------------------------------
#define TL 128

__global__ __launch_bounds__(128) void natt_kernel(
    const float* __restrict__ qkv, const float* __restrict__ rpb,
    float* __restrict__ ao)
{
    __shared__ float ks[134][33];
    __shared__ float vs[134][33];

    const int b  = blockIdx.z;
    const int h  = blockIdx.y;
    const int l0 = blockIdx.x * TL;
    const int tid = threadIdx.x;

    const int ni0 = min(max(l0 - (K_ / 2), 0), L_ - K_);
    const int niL = min(max(l0 + TL - 1 - (K_ / 2), 0), L_ - K_);
    const int range = niL + K_ - ni0;   // <= 134

    // Stage K and V rows (coalesced: each warp reads 128B contiguous)
    for (int i = tid; i < range * D_; i += TL) {
        int r = i >> 5, d = i & 31;
        size_t base = ((size_t)(b * L_ + ni0 + r)) * (3 * C_) + h * D_ + d;
        ks[r][d] = qkv[base + C_];
        vs[r][d] = qkv[base + 2 * C_];
    }
    __syncthreads();

    const int l = l0 + tid;
    const float* qp = qkv + (size_t)(b * L_ + l) * (3 * C_) + h * D_;

    float q[D_];
#pragma unroll
    for (int d4 = 0; d4 < D_ / 4; d4++) {
        float4 v = *(const float4*)(qp + d4 * 4);
        q[d4 * 4 + 0] = v.x * SCALE_;
        q[d4 * 4 + 1] = v.y * SCALE_;
        q[d4 * 4 + 2] = v.z * SCALE_;
        q[d4 * 4 + 3] = v.w * SCALE_;
    }

    const int ni = min(max(l - (K_ / 2), 0), L_ - K_);
    float a[K_];
#pragma unroll
    for (int j = 0; j < K_; j++) {
        int r = ni + j - ni0;
        float dot = 0.f;
#pragma unroll
        for (int d = 0; d < D_; d++) dot += q[d] * ks[r][d];
        a[j] = dot + rpb[h * (2 * K_ - 1) + (ni + j - l + (K_ - 1))];
    }

    float m = a[0];
#pragma unroll
    for (int j = 1; j < K_; j++) m = fmaxf(m, a[j]);
    float s = 0.f;
#pragma unroll
    for (int j = 0; j < K_; j++) { a[j] = __expf(a[j] - m); s += a[j]; }
    float inv = 1.f / s;

    float o[D_];
#pragma unroll
    for (int d = 0; d < D_; d++) o[d] = 0.f;
#pragma unroll
    for (int j = 0; j < K_; j++) {
        float p = a[j] * inv;
        int r = ni + j - ni0;
#pragma unroll
        for (int d = 0; d < D_; d++) o[d] += p * vs[r][d];
    }

    float* op = ao + (size_t)(b * L_ + l) * C_ + h * D_;
#pragma unroll
    for (int d4 = 0; d4 < D_ / 4; d4++) {
        float4 v;
        v.x = o[d4 * 4 + 0]; v.y = o[d4 * 4 + 1];
        v.z = o[d4 * 4 + 2]; v.w = o[d4 * 4 + 3];
        *(float4*)(op + d4 * 4) = v;
    }
}

// ---------------------------------------------------------------------------
extern "C" void kernel_launch(void* const* d_in, const int* in_sizes, int n_in,
                              void* d_out, int out_size)
{
    const float* x      = (const float*)d_in[0];
    const float* qkv_w  = (const float*)d_in[1];
    const float* qkv_b  = (const float*)d_in[2];
    const float* rpb    = (const float*)d_in[3];
    const float* proj_w = (const float*)d_in[4];
    const float* proj_b = (const float*)d_in[5];
    float* out = (float*)d_out;

    float *qkv, *ao;
    cudaGetSymbolAddress((void**)&qkv, g_qkv);
    cudaGetSymbolAddress((void**)&ao,  g_ao);

    const int M = B_ * L_;            // 32768

    // 1) QKV = x @ qkv_w^T + qkv_b    (M x 1536)
    {
        dim3 grid((3 * C_) / BN, M / BM);
        gemm_nt_bias<<<grid, 256>>>(x, qkv_w, qkv_b, qkv, M, 3 * C_, C_);
    }

    // 2) Neighborhood attention -> ao (M x 512)
    {
        dim3 grid(L_ / TL, H_, B_);
        natt_kernel<<<grid, TL>>>(qkv, rpb, ao);
    }

    // 3) out = ao @ proj_w^T + proj_b (M x 512)
    {
        dim3 grid(C_ / BN, M / BM);
        gemm_nt_bias<<<grid, 256>>>(ao, proj_w, proj_b, out, M, C_, C_);
    }
}

// round 2
// speedup vs baseline: 2.4682x; 2.4682x over previous
#include <cuda_runtime.h>
#include <cstdint>

// Problem constants
#define B_  2
#define L_  16384
#define C_  512
#define H_  16
#define D_  32
#define K_  7
#define SCALE_ 0.17677669529663687f   // 32^-0.5

// Scratch (device globals: no allocation allowed in kernel_launch)
__device__ float g_qkv[(size_t)B_ * L_ * 3 * C_];   // (B*L, 1536)
__device__ float g_ao [(size_t)B_ * L_ * C_];       // (B*L, 512)

// ---------------------------------------------------------------------------
// TF32 tensor-core GEMM: C[M,N] = A[M,K] @ W[N,K]^T + bias[N]
// Block 128x128x16, 256 threads (8 warps), warp tile 64x32 via m16n8k8 tf32.
// Smem stride 20 floats => conflict-free fragment loads.
// Assumes M%128==0, N%128==0, K%16==0.
// ---------------------------------------------------------------------------
#define BM 128
#define BN 128
#define BK 16
#define PAD 20

__device__ __forceinline__ float tf32r(float x) {
    unsigned r;
    asm("cvt.rna.tf32.f32 %0, %1;" : "=r"(r) : "f"(x));
    return __uint_as_float(r);
}

__device__ __forceinline__ void mma8(float* d, const unsigned* a, const unsigned* b) {
    asm volatile(
        "mma.sync.aligned.m16n8k8.row.col.f32.tf32.tf32.f32 "
        "{%0,%1,%2,%3},{%4,%5,%6,%7},{%8,%9},{%0,%1,%2,%3};\n"
        : "+f"(d[0]), "+f"(d[1]), "+f"(d[2]), "+f"(d[3])
        : "r"(a[0]), "r"(a[1]), "r"(a[2]), "r"(a[3]), "r"(b[0]), "r"(b[1]));
}

__global__ __launch_bounds__(256) void gemm_tf32_bias(
    const float* __restrict__ A, const float* __restrict__ W,
    const float* __restrict__ bias, float* __restrict__ C,
    int M, int N, int K)
{
    __shared__ float As[2][BM * PAD];
    __shared__ float Bs[2][BN * PAD];

    const int tid  = threadIdx.x;
    const int lane = tid & 31;
    const int warp = tid >> 5;
    const int g    = lane >> 2;     // 0..7
    const int tq   = lane & 3;      // 0..3

    const int bm = blockIdx.y * BM;
    const int bn = blockIdx.x * BN;
    const int wm0 = (warp >> 2) * 64;   // warp M origin in tile (0 or 64)
    const int wn0 = (warp & 3) * 32;    // warp N origin in tile (0..96)

    const float* Ab = A + (size_t)bm * K;
    const float* Wb = W + (size_t)bn * K;

    // Per-thread staging indices: idx in [0,512) over 2 steps, m=idx>>2, k4=(idx&3)*4
    const int m0 = tid >> 2;           // 0..63
    const int m1 = (tid + 256) >> 2;   // 64..127
    const int k4 = (tid & 3) * 4;      // 0,4,8,12

    float acc[4][4][4];
#pragma unroll
    for (int i = 0; i < 4; i++)
#pragma unroll
        for (int j = 0; j < 4; j++)
#pragma unroll
            for (int c = 0; c < 4; c++) acc[i][j][c] = 0.f;

    const int NIT = K / BK;

    float4 pa0, pa1, pb0, pb1;

    // Prefetch tile 0
    pa0 = *(const float4*)(Ab + (size_t)m0 * K + k4);
    pa1 = *(const float4*)(Ab + (size_t)m1 * K + k4);
    pb0 = *(const float4*)(Wb + (size_t)m0 * K + k4);
    pb1 = *(const float4*)(Wb + (size_t)m1 * K + k4);

    // Convert + store tile 0
    {
        float4 c0 = make_float4(tf32r(pa0.x), tf32r(pa0.y), tf32r(pa0.z), tf32r(pa0.w));
        float4 c1 = make_float4(tf32r(pa1.x), tf32r(pa1.y), tf32r(pa1.z), tf32r(pa1.w));
        *(float4*)&As[0][m0 * PAD + k4] = c0;
        *(float4*)&As[0][m1 * PAD + k4] = c1;
        float4 d0 = make_float4(tf32r(pb0.x), tf32r(pb0.y), tf32r(pb0.z), tf32r(pb0.w));
        float4 d1 = make_float4(tf32r(pb1.x), tf32r(pb1.y), tf32r(pb1.z), tf32r(pb1.w));
        *(float4*)&Bs[0][m0 * PAD + k4] = d0;
        *(float4*)&Bs[0][m1 * PAD + k4] = d1;
    }
    __syncthreads();

    int buf = 0;
    for (int it = 0; it < NIT; ++it) {
        // Prefetch next tile (global loads issued before compute)
        if (it + 1 < NIT) {
            int ko = (it + 1) * BK + k4;
            pa0 = *(const float4*)(Ab + (size_t)m0 * K + ko);
            pa1 = *(const float4*)(Ab + (size_t)m1 * K + ko);
            pb0 = *(const float4*)(Wb + (size_t)m0 * K + ko);
            pb1 = *(const float4*)(Wb + (size_t)m1 * K + ko);
        }

        // Compute on current buffer: 2 k-steps of 8
        const float* as = As[buf];
        const float* bs = Bs[buf];
#pragma unroll
        for (int ks = 0; ks < 2; ks++) {
            const int kb = ks * 8;
            unsigned af[4][4];
#pragma unroll
            for (int mt = 0; mt < 4; mt++) {
                int r0 = wm0 + mt * 16 + g;
                af[mt][0] = __float_as_uint(as[r0 * PAD + kb + tq]);
                af[mt][1] = __float_as_uint(as[(r0 + 8) * PAD + kb + tq]);
                af[mt][2] = __float_as_uint(as[r0 * PAD + kb + tq + 4]);
                af[mt][3] = __float_as_uint(as[(r0 + 8) * PAD + kb + tq + 4]);
            }
            unsigned bf[4][2];
#pragma unroll
            for (int nt = 0; nt < 4; nt++) {
                int c0 = wn0 + nt * 8 + g;
                bf[nt][0] = __float_as_uint(bs[c0 * PAD + kb + tq]);
                bf[nt][1] = __float_as_uint(bs[c0 * PAD + kb + tq + 4]);
            }
#pragma unroll
            for (int mt = 0; mt < 4; mt++)
#pragma unroll
                for (int nt = 0; nt < 4; nt++)
                    mma8(acc[mt][nt], af[mt], bf[nt]);
        }

        // Store next tile into the other buffer
        if (it + 1 < NIT) {
            int nb = buf ^ 1;
            float4 c0 = make_float4(tf32r(pa0.x), tf32r(pa0.y), tf32r(pa0.z), tf32r(pa0.w));
            float4 c1 = make_float4(tf32r(pa1.x), tf32r(pa1.y), tf32r(pa1.z), tf32r(pa1.w));
            *(float4*)&As[nb][m0 * PAD + k4] = c0;
            *(float4*)&As[nb][m1 * PAD + k4] = c1;
            float4 d0 = make_float4(tf32r(pb0.x), tf32r(pb0.y), tf32r(pb0.z), tf32r(pb0.w));
            float4 d1 = make_float4(tf32r(pb1.x), tf32r(pb1.y), tf32r(pb1.z), tf32r(pb1.w));
            *(float4*)&Bs[nb][m0 * PAD + k4] = d0;
            *(float4*)&Bs[nb][m1 * PAD + k4] = d1;
        }
        __syncthreads();
        buf ^= 1;
    }

    // Epilogue: bias + store (float2 per half-tile row)
#pragma unroll
    for (int nt = 0; nt < 4; nt++) {
        int col = bn + wn0 + nt * 8 + tq * 2;
        float2 bb = *(const float2*)&bias[col];
#pragma unroll
        for (int mt = 0; mt < 4; mt++) {
            int row = bm + wm0 + mt * 16 + g;
            float2 o0, o1;
            o0.x = acc[mt][nt][0] + bb.x; o0.y = acc[mt][nt][1] + bb.y;
            o1.x = acc[mt][nt][2] + bb.x; o1.y = acc[mt][nt][3] + bb.y;
            *(float2*)(C + (size_t)row * N + col) = o0;
            *(float2*)(C + (size_t)(row + 8) * N + col) = o1;
        }
    }
}

// ---------------------------------------------------------------------------
// Neighborhood attention, K=7, D=32. (unchanged from round 1)
// ---------------------------------------------------------------------------
#define TL 128

__global__ __launch_bounds__(128) void natt_kernel(
    const float* __restrict__ qkv, const float* __restrict__ rpb,
    float* __restrict__ ao)
{
    __shared__ float ks[134][33];
    __shared__ float vs[134][33];

    const int b  = blockIdx.z;
    const int h  = blockIdx.y;
    const int l0 = blockIdx.x * TL;
    const int tid = threadIdx.x;

    const int ni0 = min(max(l0 - (K_ / 2), 0), L_ - K_);
    const int niL = min(max(l0 + TL - 1 - (K_ / 2), 0), L_ - K_);
    const int range = niL + K_ - ni0;   // <= 134

    for (int i = tid; i < range * D_; i += TL) {
        int r = i >> 5, d = i & 31;
        size_t base = ((size_t)(b * L_ + ni0 + r)) * (3 * C_) + h * D_ + d;
        ks[r][d] = qkv[base + C_];
        vs[r][d] = qkv[base + 2 * C_];
    }
    __syncthreads();

    const int l = l0 + tid;
    const float* qp = qkv + (size_t)(b * L_ + l) * (3 * C_) + h * D_;

    float q[D_];
#pragma unroll
    for (int d4 = 0; d4 < D_ / 4; d4++) {
        float4 v = *(const float4*)(qp + d4 * 4);
        q[d4 * 4 + 0] = v.x * SCALE_;
        q[d4 * 4 + 1] = v.y * SCALE_;
        q[d4 * 4 + 2] = v.z * SCALE_;
        q[d4 * 4 + 3] = v.w * SCALE_;
    }

    const int ni = min(max(l - (K_ / 2), 0), L_ - K_);
    float a[K_];
#pragma unroll
    for (int j = 0; j < K_; j++) {
        int r = ni + j - ni0;
        float dot = 0.f;
#pragma unroll
        for (int d = 0; d < D_; d++) dot += q[d] * ks[r][d];
        a[j] = dot + rpb[h * (2 * K_ - 1) + (ni + j - l + (K_ - 1))];
    }

    float m = a[0];
#pragma unroll
    for (int j = 1; j < K_; j++) m = fmaxf(m, a[j]);
    float s = 0.f;
#pragma unroll
    for (int j = 0; j < K_; j++) { a[j] = __expf(a[j] - m); s += a[j]; }
    float inv = 1.f / s;

    float o[D_];
#pragma unroll
    for (int d = 0; d < D_; d++) o[d] = 0.f;
#pragma unroll
    for (int j = 0; j < K_; j++) {
        float p = a[j] * inv;
        int r = ni + j - ni0;
#pragma unroll
        for (int d = 0; d < D_; d++) o[d] += p * vs[r][d];
    }

    float* op = ao + (size_t)(b * L_ + l) * C_ + h * D_;
#pragma unroll
    for (int d4 = 0; d4 < D_ / 4; d4++) {
        float4 v;
        v.x = o[d4 * 4 + 0]; v.y = o[d4 * 4 + 1];
        v.z = o[d4 * 4 + 2]; v.w = o[d4 * 4 + 3];
        *(float4*)(op + d4 * 4) = v;
    }
}

// ---------------------------------------------------------------------------
extern "C" void kernel_launch(void* const* d_in, const int* in_sizes, int n_in,
                              void* d_out, int out_size)
{
    const float* x      = (const float*)d_in[0];
    const float* qkv_w  = (const float*)d_in[1];
    const float* qkv_b  = (const float*)d_in[2];
    const float* rpb    = (const float*)d_in[3];
    const float* proj_w = (const float*)d_in[4];
    const float* proj_b = (const float*)d_in[5];
    float* out = (float*)d_out;

    float *qkv, *ao;
    cudaGetSymbolAddress((void**)&qkv, g_qkv);
    cudaGetSymbolAddress((void**)&ao,  g_ao);

    const int M = B_ * L_;            // 32768

    // 1) QKV = x @ qkv_w^T + qkv_b    (M x 1536)
    {
        dim3 grid((3 * C_) / BN, M / BM);
        gemm_tf32_bias<<<grid, 256>>>(x, qkv_w, qkv_b, qkv, M, 3 * C_, C_);
    }

    // 2) Neighborhood attention -> ao (M x 512)
    {
        dim3 grid(L_ / TL, H_, B_);
        natt_kernel<<<grid, TL>>>(qkv, rpb, ao);
    }

    // 3) out = ao @ proj_w^T + proj_b (M x 512)
    {
        dim3 grid(C_ / BN, M / BM);
        gemm_tf32_bias<<<grid, 256>>>(ao, proj_w, proj_b, out, M, C_, C_);
    }
}

// round 3
// speedup vs baseline: 2.4739x; 1.0023x over previous
#include <cuda_runtime.h>
#include <cstdint>

// Problem constants
#define B_  2
#define L_  16384
#define C_  512
#define H_  16
#define D_  32
#define K_  7
#define SCALE_ 0.17677669529663687f   // 32^-0.5

// Scratch (device globals: no allocation allowed in kernel_launch)
__device__ float g_qkv[(size_t)B_ * L_ * 3 * C_];   // (B*L, 1536)
__device__ float g_ao [(size_t)B_ * L_ * C_];       // (B*L, 512)

// ---------------------------------------------------------------------------
// TF32 tensor-core GEMM: C[M,N] = A[M,K] @ W[N,K]^T + bias[N]
// Block 128x256x16, 256 threads (8 warps), warp tile 64x64 via m16n8k8 tf32.
// Smem stride 20 floats => conflict-free fragment loads.
// Assumes M%128==0, N%256==0, K%16==0.
// ---------------------------------------------------------------------------
#define BM 128
#define BN 256
#define BK 16
#define PAD 20

__device__ __forceinline__ float tf32r(float x) {
    unsigned r;
    asm("cvt.rna.tf32.f32 %0, %1;" : "=r"(r) : "f"(x));
    return __uint_as_float(r);
}

__device__ __forceinline__ void mma8(float* d, const unsigned* a, const unsigned* b) {
    asm volatile(
        "mma.sync.aligned.m16n8k8.row.col.f32.tf32.tf32.f32 "
        "{%0,%1,%2,%3},{%4,%5,%6,%7},{%8,%9},{%0,%1,%2,%3};\n"
        : "+f"(d[0]), "+f"(d[1]), "+f"(d[2]), "+f"(d[3])
        : "r"(a[0]), "r"(a[1]), "r"(a[2]), "r"(a[3]), "r"(b[0]), "r"(b[1]));
}

__global__ __launch_bounds__(256, 1) void gemm_tf32_bias(
    const float* __restrict__ A, const float* __restrict__ W,
    const float* __restrict__ bias, float* __restrict__ C,
    int M, int N, int K)
{
    __shared__ float As[2][BM * PAD];
    __shared__ float Bs[2][BN * PAD];

    const int tid  = threadIdx.x;
    const int lane = tid & 31;
    const int warp = tid >> 5;
    const int g    = lane >> 2;     // 0..7
    const int tq   = lane & 3;      // 0..3

    const int bm = blockIdx.y * BM;
    const int bn = blockIdx.x * BN;
    const int wm0 = (warp >> 2) * 64;   // 0 or 64
    const int wn0 = (warp & 3) * 64;    // 0,64,128,192

    const float* Ab = A + (size_t)bm * K;
    const float* Wb = W + (size_t)bn * K;

    // Staging: A = 512 float4 (2/thread), B = 1024 float4 (4/thread)
    const int srow = tid >> 2;          // 0..63
    const int sk4  = (tid & 3) * 4;     // 0,4,8,12

    float acc[4][8][4];
#pragma unroll
    for (int i = 0; i < 4; i++)
#pragma unroll
        for (int j = 0; j < 8; j++)
#pragma unroll
            for (int c = 0; c < 4; c++) acc[i][j][c] = 0.f;

    const int NIT = K / BK;

    float4 pa[2], pb[4];

    // Prefetch tile 0
#pragma unroll
    for (int s = 0; s < 2; s++)
        pa[s] = *(const float4*)(Ab + (size_t)(srow + s * 64) * K + sk4);
#pragma unroll
    for (int s = 0; s < 4; s++)
        pb[s] = *(const float4*)(Wb + (size_t)(srow + s * 64) * K + sk4);

    // Convert + store tile 0
#pragma unroll
    for (int s = 0; s < 2; s++) {
        float4 c = make_float4(tf32r(pa[s].x), tf32r(pa[s].y), tf32r(pa[s].z), tf32r(pa[s].w));
        *(float4*)&As[0][(srow + s * 64) * PAD + sk4] = c;
    }
#pragma unroll
    for (int s = 0; s < 4; s++) {
        float4 c = make_float4(tf32r(pb[s].x), tf32r(pb[s].y), tf32r(pb[s].z), tf32r(pb[s].w));
        *(float4*)&Bs[0][(srow + s * 64) * PAD + sk4] = c;
    }
    __syncthreads();

    int buf = 0;
    for (int it = 0; it < NIT; ++it) {
        // Prefetch next tile
        if (it + 1 < NIT) {
            int ko = (it + 1) * BK + sk4;
#pragma unroll
            for (int s = 0; s < 2; s++)
                pa[s] = *(const float4*)(Ab + (size_t)(srow + s * 64) * K + ko);
#pragma unroll
            for (int s = 0; s < 4; s++)
                pb[s] = *(const float4*)(Wb + (size_t)(srow + s * 64) * K + ko);
        }

        const float* as = As[buf];
        const float* bs = Bs[buf];
#pragma unroll
        for (int ks = 0; ks < 2; ks++) {
            const int kb = ks * 8;
            unsigned af[4][4];
#pragma unroll
            for (int mt = 0; mt < 4; mt++) {
                int r0 = (wm0 + mt * 16 + g) * PAD + kb + tq;
                af[mt][0] = __float_as_uint(as[r0]);
                af[mt][1] = __float_as_uint(as[r0 + 8 * PAD]);
                af[mt][2] = __float_as_uint(as[r0 + 4]);
                af[mt][3] = __float_as_uint(as[r0 + 8 * PAD + 4]);
            }
            unsigned bf[8][2];
#pragma unroll
            for (int nt = 0; nt < 8; nt++) {
                int c0 = (wn0 + nt * 8 + g) * PAD + kb + tq;
                bf[nt][0] = __float_as_uint(bs[c0]);
                bf[nt][1] = __float_as_uint(bs[c0 + 4]);
            }
#pragma unroll
            for (int mt = 0; mt < 4; mt++)
#pragma unroll
                for (int nt = 0; nt < 8; nt++)
                    mma8(acc[mt][nt], af[mt], bf[nt]);
        }

        // Store next tile into the other buffer
        if (it + 1 < NIT) {
            int nb = buf ^ 1;
#pragma unroll
            for (int s = 0; s < 2; s++) {
                float4 c = make_float4(tf32r(pa[s].x), tf32r(pa[s].y), tf32r(pa[s].z), tf32r(pa[s].w));
                *(float4*)&As[nb][(srow + s * 64) * PAD + sk4] = c;
            }
#pragma unroll
            for (int s = 0; s < 4; s++) {
                float4 c = make_float4(tf32r(pb[s].x), tf32r(pb[s].y), tf32r(pb[s].z), tf32r(pb[s].w));
                *(float4*)&Bs[nb][(srow + s * 64) * PAD + sk4] = c;
            }
        }
        __syncthreads();
        buf ^= 1;
    }

    // Epilogue: bias + store
#pragma unroll
    for (int nt = 0; nt < 8; nt++) {
        int col = bn + wn0 + nt * 8 + tq * 2;
        float2 bb = *(const float2*)&bias[col];
#pragma unroll
        for (int mt = 0; mt < 4; mt++) {
            int row = bm + wm0 + mt * 16 + g;
            float2 o0, o1;
            o0.x = acc[mt][nt][0] + bb.x; o0.y = acc[mt][nt][1] + bb.y;
            o1.x = acc[mt][nt][2] + bb.x; o1.y = acc[mt][nt][3] + bb.y;
            *(float2*)(C + (size_t)row * N + col) = o0;
            *(float2*)(C + (size_t)(row + 8) * N + col) = o1;
        }
    }
}

// ---------------------------------------------------------------------------
// Neighborhood attention, K=7, D=32.
// ---------------------------------------------------------------------------
#define TL 128

__global__ __launch_bounds__(128) void natt_kernel(
    const float* __restrict__ qkv, const float* __restrict__ rpb,
    float* __restrict__ ao)
{
    __shared__ float ks[134][33];
    __shared__ float vs[134][33];

    const int b  = blockIdx.z;
    const int h  = blockIdx.y;
    const int l0 = blockIdx.x * TL;
    const int tid = threadIdx.x;

    const int ni0 = min(max(l0 - (K_ / 2), 0), L_ - K_);
    const int niL = min(max(l0 + TL - 1 - (K_ / 2), 0), L_ - K_);
    const int range = niL + K_ - ni0;   // <= 134

    for (int i = tid; i < range * D_; i += TL) {
        int r = i >> 5, d = i & 31;
        size_t base = ((size_t)(b * L_ + ni0 + r)) * (3 * C_) + h * D_ + d;
        ks[r][d] = qkv[base + C_];
        vs[r][d] = qkv[base + 2 * C_];
    }
    __syncthreads();

    const int l = l0 + tid;
    const float* qp = qkv + (size_t)(b * L_ + l) * (3 * C_) + h * D_;

    float q[D_];
#pragma unroll
    for (int d4 = 0; d4 < D_ / 4; d4++) {
        float4 v = *(const float4*)(qp + d4 * 4);
        q[d4 * 4 + 0] = v.x * SCALE_;
        q[d4 * 4 + 1] = v.y * SCALE_;
        q[d4 * 4 + 2] = v.z * SCALE_;
        q[d4 * 4 + 3] = v.w * SCALE_;
    }

    const int ni = min(max(l - (K_ / 2), 0), L_ - K_);
    float a[K_];
#pragma unroll
    for (int j = 0; j < K_; j++) {
        int r = ni + j - ni0;
        float dot = 0.f;
#pragma unroll
        for (int d = 0; d < D_; d++) dot += q[d] * ks[r][d];
        a[j] = dot + rpb[h * (2 * K_ - 1) + (ni + j - l + (K_ - 1))];
    }

    float m = a[0];
#pragma unroll
    for (int j = 1; j < K_; j++) m = fmaxf(m, a[j]);
    float s = 0.f;
#pragma unroll
    for (int j = 0; j < K_; j++) { a[j] = __expf(a[j] - m); s += a[j]; }
    float inv = 1.f / s;

    float o[D_];
#pragma unroll
    for (int d = 0; d < D_; d++) o[d] = 0.f;
#pragma unroll
    for (int j = 0; j < K_; j++) {
        float p = a[j] * inv;
        int r = ni + j - ni0;
#pragma unroll
        for (int d = 0; d < D_; d++) o[d] += p * vs[r][d];
    }

    float* op = ao + (size_t)(b * L_ + l) * C_ + h * D_;
#pragma unroll
    for (int d4 = 0; d4 < D_ / 4; d4++) {
        float4 v;
        v.x = o[d4 * 4 + 0]; v.y = o[d4 * 4 + 1];
        v.z = o[d4 * 4 + 2]; v.w = o[d4 * 4 + 3];
        *(float4*)(op + d4 * 4) = v;
    }
}

// ---------------------------------------------------------------------------
extern "C" void kernel_launch(void* const* d_in, const int* in_sizes, int n_in,
                              void* d_out, int out_size)
{
    const float* x      = (const float*)d_in[0];
    const float* qkv_w  = (const float*)d_in[1];
    const float* qkv_b  = (const float*)d_in[2];
    const float* rpb    = (const float*)d_in[3];
    const float* proj_w = (const float*)d_in[4];
    const float* proj_b = (const float*)d_in[5];
    float* out = (float*)d_out;

    float *qkv, *ao;
    cudaGetSymbolAddress((void**)&qkv, g_qkv);
    cudaGetSymbolAddress((void**)&ao,  g_ao);

    const int M = B_ * L_;            // 32768

    // 1) QKV = x @ qkv_w^T + qkv_b    (M x 1536)
    {
        dim3 grid((3 * C_) / BN, M / BM);
        gemm_tf32_bias<<<grid, 256>>>(x, qkv_w, qkv_b, qkv, M, 3 * C_, C_);
    }

    // 2) Neighborhood attention -> ao (M x 512)
    {
        dim3 grid(L_ / TL, H_, B_);
        natt_kernel<<<grid, TL>>>(qkv, rpb, ao);
    }

    // 3) out = ao @ proj_w^T + proj_b (M x 512)
    {
        dim3 grid(C_ / BN, M / BM);
        gemm_tf32_bias<<<grid, 256>>>(ao, proj_w, proj_b, out, M, C_, C_);
    }
}

// round 5
// speedup vs baseline: 3.8615x; 1.5609x over previous
#include <cuda_runtime.h>
#include <cuda_fp16.h>
#include <cstdint>

// Problem constants
#define B_  2
#define L_  16384
#define C_  512
#define H_  16
#define D_  32
#define K_  7
#define SCALE_ 0.17677669529663687f   // 32^-0.5

// Scratch (device globals)
__device__ float  g_qkv[(size_t)B_ * L_ * 3 * C_];   // (B*L, 1536) fp32
__device__ __half g_aoh[(size_t)B_ * L_ * C_];       // attention out, fp16
__device__ __half g_xh [(size_t)B_ * L_ * C_];       // x, fp16
__device__ __half g_w1h[(size_t)3 * C_ * C_];        // qkv_w, fp16
__device__ __half g_w2h[(size_t)C_ * C_];            // proj_w, fp16

// Elementwise f32 -> f16 (rn); n4 = element count / 4
__global__ void cvt_half_kernel(const float* __restrict__ in,
                                __half* __restrict__ out, int n4)
{
    int i = blockIdx.x * blockDim.x + threadIdx.x;
    if (i < n4) {
        float4 v = ((const float4*)in)[i];
        __half2 h0 = __floats2half2_rn(v.x, v.y);
        __half2 h1 = __floats2half2_rn(v.z, v.w);
        uint2 p;
        p.x = *(unsigned*)&h0;
        p.y = *(unsigned*)&h1;
        ((uint2*)out)[i] = p;
    }
}

// ---------------------------------------------------------------------------
// FP16 tensor-core GEMM (f32 accum): C[M,N] = A[M,K] @ W[N,K]^T + bias[N]
// Block 128x256x32, 256 threads (8 warps), warp tile 64x64, mma.m16n8k16,
// ldmatrix.x4 fragments, cp.async 3-stage pipeline.
// Requires M%128==0, N%256==0, K%32==0.
// ---------------------------------------------------------------------------
#define GBM 128
#define GBN 256
#define GBK 32
#define ROWH 40                       // halves per smem row (32 data + 8 pad)
#define ROWB (ROWH * 2)               // 80 bytes
#define A_BYT (GBM * ROWB)            // 10240
#define B_BYT (GBN * ROWB)            // 20480
#define STG   (A_BYT + B_BYT)         // 30720
#define NSTG  3
#define SMEM_REQ (NSTG * STG)         // 92160

__device__ __forceinline__ void mma16(float* d, const unsigned* a, const unsigned* b) {
    asm volatile(
        "mma.sync.aligned.m16n8k16.row.col.f32.f16.f16.f32 "
        "{%0,%1,%2,%3},{%4,%5,%6,%7},{%8,%9},{%0,%1,%2,%3};\n"
        : "+f"(d[0]), "+f"(d[1]), "+f"(d[2]), "+f"(d[3])
        : "r"(a[0]), "r"(a[1]), "r"(a[2]), "r"(a[3]), "r"(b[0]), "r"(b[1]));
}

__device__ __forceinline__ void ldsm4(unsigned* r, uint32_t addr) {
    asm volatile(
        "ldmatrix.sync.aligned.m8n8.x4.shared.b16 {%0,%1,%2,%3}, [%4];"
        : "=r"(r[0]), "=r"(r[1]), "=r"(r[2]), "=r"(r[3]) : "r"(addr));
}

__global__ __launch_bounds__(256, 1) void gemm_f16(
    const __half* __restrict__ A, const __half* __restrict__ W,
    const float* __restrict__ bias, float* __restrict__ Co,
    int M, int N, int Kd)
{
    extern __shared__ char smem_raw[];
    uint32_t base;
    asm("{ .reg .u64 t; cvta.to.shared.u64 t, %1; cvt.u32.u64 %0, t; }"
        : "=r"(base) : "l"(smem_raw));

    const int tid  = threadIdx.x;
    const int lane = tid & 31;
    const int warp = tid >> 5;
    const int bm = blockIdx.y * GBM;
    const int bn = blockIdx.x * GBN;
    const int wm0 = (warp >> 2) * 64;
    const int wn0 = (warp & 3) * 64;
    const int NT = Kd / GBK;

    float acc[4][8][4];
#pragma unroll
    for (int i = 0; i < 4; i++)
#pragma unroll
        for (int j = 0; j < 8; j++)
#pragma unroll
            for (int c = 0; c < 4; c++) acc[i][j][c] = 0.f;

    // Stage loader: tile kt -> slot
    auto load_stage = [&](int kt, int slot) {
        const int k0 = kt * GBK;
        const uint32_t sa = base + slot * STG;
        const uint32_t sb = sa + A_BYT;
        // A: 128 rows x 4 chunks(16B)
#pragma unroll
        for (int i = 0; i < 2; i++) {
            int idx = tid + i * 256;
            int r = idx >> 2, c = idx & 3;
            uint32_t dst = sa + r * ROWB + c * 16;
            const __half* src = A + (size_t)(bm + r) * Kd + k0 + c * 8;
            asm volatile("cp.async.cg.shared.global [%0], [%1], 16;"
                         :: "r"(dst), "l"(src));
        }
        // B: 256 rows x 4 chunks
#pragma unroll
        for (int i = 0; i < 4; i++) {
            int idx = tid + i * 256;
            int r = idx >> 2, c = idx & 3;
            uint32_t dst = sb + r * ROWB + c * 16;
            const __half* src = W + (size_t)(bn + r) * Kd + k0 + c * 8;
            asm volatile("cp.async.cg.shared.global [%0], [%1], 16;"
                         :: "r"(dst), "l"(src));
        }
        asm volatile("cp.async.commit_group;");
    };

    // ldmatrix lane addressing (constant per thread)
    const int a_row = (lane & 15);          // + wm0 + mt*16
    const int a_k8  = (lane >> 4) * 8;      // 0 or 8
    const int b_row = (lane & 7) + ((lane >> 4) & 1) * 8;  // + wn0 + p*16
    const int b_k8  = ((lane >> 3) & 1) * 8;

    // Prologue
    load_stage(0, 0);
    load_stage(1, 1);

    for (int kt = 0; kt < NT; kt++) {
        const int slot = kt - (kt / NSTG) * NSTG;

        if (kt == NT - 1) asm volatile("cp.async.wait_group 0;");
        else              asm volatile("cp.async.wait_group 1;");
        __syncthreads();

        if (kt + 2 < NT) load_stage(kt + 2, (kt + 2) % NSTG);

        const uint32_t sa = base + slot * STG;
        const uint32_t sb = sa + A_BYT;

#pragma unroll
        for (int ks = 0; ks < 2; ks++) {
            const int kb = ks * 16;
            unsigned af[4][4];
#pragma unroll
            for (int mt = 0; mt < 4; mt++)
                ldsm4(af[mt], sa + (wm0 + mt * 16 + a_row) * ROWB + (kb + a_k8) * 2);
            unsigned bf[8][2];
#pragma unroll
            for (int p = 0; p < 4; p++) {
                unsigned t[4];
                ldsm4(t, sb + (wn0 + p * 16 + b_row) * ROWB + (kb + b_k8) * 2);
                bf[p * 2 + 0][0] = t[0]; bf[p * 2 + 0][1] = t[1];
                bf[p * 2 + 1][0] = t[2]; bf[p * 2 + 1][1] = t[3];
            }
#pragma unroll
            for (int mt = 0; mt < 4; mt++)
#pragma unroll
                for (int nt = 0; nt < 8; nt++)
                    mma16(acc[mt][nt], af[mt], bf[nt]);
        }
        __syncthreads();
    }

    // Epilogue: bias + store
    const int g  = lane >> 2;
    const int tq = lane & 3;
#pragma unroll
    for (int nt = 0; nt < 8; nt++) {
        int col = bn + wn0 + nt * 8 + tq * 2;
        float2 bb = *(const float2*)&bias[col];
#pragma unroll
        for (int mt = 0; mt < 4; mt++) {
            int row = bm + wm0 + mt * 16 + g;
            float2 o0, o1;
            o0.x = acc[mt][nt][0] + bb.x; o0.y = acc[mt][nt][1] + bb.y;
            o1.x = acc[mt][nt][2] + bb.x; o1.y = acc[mt][nt][3] + bb.y;
            *(float2*)(Co + (size_t)row * N + col) = o0;
            *(float2*)(Co + (size_t)(row + 8) * N + col) = o1;
        }
    }
}

// ---------------------------------------------------------------------------
// Neighborhood attention, K=7, D=32. fp32 in, fp16 out (feeds GEMM2).
// ---------------------------------------------------------------------------
#define TL 128

__global__ __launch_bounds__(128) void natt_kernel(
    const float* __restrict__ qkv, const float* __restrict__ rpb,
    __half* __restrict__ ao)
{
    __shared__ float ks[134][33];
    __shared__ float vs[134][33];

    const int b  = blockIdx.z;
    const int h  = blockIdx.y;
    const int l0 = blockIdx.x * TL;
    const int tid = threadIdx.x;

    const int ni0 = min(max(l0 - (K_ / 2), 0), L_ - K_);
    const int niL = min(max(l0 + TL - 1 - (K_ / 2), 0), L_ - K_);
    const int range = niL + K_ - ni0;   // <= 134

    for (int i = tid; i < range * D_; i += TL) {
        int r = i >> 5, d = i & 31;
        size_t base = ((size_t)(b * L_ + ni0 + r)) * (3 * C_) + h * D_ + d;
        ks[r][d] = qkv[base + C_];
        vs[r][d] = qkv[base + 2 * C_];
    }
    __syncthreads();

    const int l = l0 + tid;
    const float* qp = qkv + (size_t)(b * L_ + l) * (3 * C_) + h * D_;

    float q[D_];
#pragma unroll
    for (int d4 = 0; d4 < D_ / 4; d4++) {
        float4 v = *(const float4*)(qp + d4 * 4);
        q[d4 * 4 + 0] = v.x * SCALE_;
        q[d4 * 4 + 1] = v.y * SCALE_;
        q[d4 * 4 + 2] = v.z * SCALE_;
        q[d4 * 4 + 3] = v.w * SCALE_;
    }

    const int ni = min(max(l - (K_ / 2), 0), L_ - K_);
    float a[K_];
#pragma unroll
    for (int j = 0; j < K_; j++) {
        int r = ni + j - ni0;
        float dot = 0.f;
#pragma unroll
        for (int d = 0; d < D_; d++) dot += q[d] * ks[r][d];
        a[j] = dot + rpb[h * (2 * K_ - 1) + (ni + j - l + (K_ - 1))];
    }

    float m = a[0];
#pragma unroll
    for (int j = 1; j < K_; j++) m = fmaxf(m, a[j]);
    float s = 0.f;
#pragma unroll
    for (int j = 0; j < K_; j++) { a[j] = __expf(a[j] - m); s += a[j]; }
    float inv = 1.f / s;

    float o[D_];
#pragma unroll
    for (int d = 0; d < D_; d++) o[d] = 0.f;
#pragma unroll
    for (int j = 0; j < K_; j++) {
        float p = a[j] * inv;
        int r = ni + j - ni0;
#pragma unroll
        for (int d = 0; d < D_; d++) o[d] += p * vs[r][d];
    }

    __half* op = ao + (size_t)(b * L_ + l) * C_ + h * D_;
#pragma unroll
    for (int d2 = 0; d2 < D_ / 2; d2++) {
        __half2 hv = __floats2half2_rn(o[d2 * 2], o[d2 * 2 + 1]);
        *(__half2*)(op + d2 * 2) = hv;
    }
}

// ---------------------------------------------------------------------------
extern "C" void kernel_launch(void* const* d_in, const int* in_sizes, int n_in,
                              void* d_out, int out_size)
{
    const float* x      = (const float*)d_in[0];
    const float* qkv_w  = (const float*)d_in[1];
    const float* qkv_b  = (const float*)d_in[2];
    const float* rpb    = (const float*)d_in[3];
    const float* proj_w = (const float*)d_in[4];
    const float* proj_b = (const float*)d_in[5];
    float* out = (float*)d_out;

    float  *qkv;
    __half *aoh, *xh, *w1h, *w2h;
    cudaGetSymbolAddress((void**)&qkv, g_qkv);
    cudaGetSymbolAddress((void**)&aoh, g_aoh);
    cudaGetSymbolAddress((void**)&xh,  g_xh);
    cudaGetSymbolAddress((void**)&w1h, g_w1h);
    cudaGetSymbolAddress((void**)&w2h, g_w2h);

    cudaFuncSetAttribute(gemm_f16,
                         cudaFuncAttributeMaxDynamicSharedMemorySize, SMEM_REQ);

    const int M = B_ * L_;            // 32768

    // 0) Convert GEMM operands to fp16
    {
        int n4 = (M * C_) / 4;
        cvt_half_kernel<<<(n4 + 255) / 256, 256>>>(x, xh, n4);
        int w1 = (3 * C_ * C_) / 4;
        cvt_half_kernel<<<(w1 + 255) / 256, 256>>>(qkv_w, w1h, w1);
        int w2 = (C_ * C_) / 4;
        cvt_half_kernel<<<(w2 + 255) / 256, 256>>>(proj_w, w2h, w2);
    }

    // 1) QKV = x @ qkv_w^T + qkv_b    (M x 1536)
    {
        dim3 grid((3 * C_) / GBN, M / GBM);
        gemm_f16<<<grid, 256, SMEM_REQ>>>(xh, w1h, qkv_b, qkv, M, 3 * C_, C_);
    }

    // 2) Neighborhood attention -> aoh (M x 512, fp16)
    {
        dim3 grid(L_ / TL, H_, B_);
        natt_kernel<<<grid, TL>>>(qkv, rpb, aoh);
    }

    // 3) out = aoh @ proj_w^T + proj_b (M x 512)
    {
        dim3 grid(C_ / GBN, M / GBM);
        gemm_f16<<<grid, 256, SMEM_REQ>>>(aoh, w2h, proj_b, out, M, C_, C_);
    }
}